// round 7
// baseline (speedup 1.0000x reference)
#include <cuda_runtime.h>

// NURBS surface eval: DEG=3, N_CP=32x32, N_EVAL=2,000,000.
// Clamped-uniform knots: knot(i) = clamp(i-3,0,29)/29, span = floor(u*29)+3.
// Output: d_out[0..4N) = points (x,y,z,1); d_out[4N..8N) = normals (nx,ny,nz,0).
//
// R7: basis via per-span cubic polynomial tables (precomputed once per block):
//   N_r(u)|span se  ==  cubic in t = u*29 - se.  29x4 coefficient float4s,
//   8x bank-column-replicated -> random-span gather is conflict-free.
//   Horner eval: no rcp, no clamps, no serial recursion chain.
//   Derivative scale factors (29, p) are uniform on both partials -> cancel in
//   the normalized cross product -> skipped. Partition of unity -> w == 1.
// Keeps R5's 8x-replicated control-point table and persistent 148x1024 launch.

#define NCP 32
#define NTHREADS 1024
#define NBLOCKS 148
#define CP_ENTRIES (NCP * NCP * 8)          // 8192 float4 = 128 KB
#define CT_ENTRIES (32 * 4 * 8)             // 1024 float4 = 16 KB (29 spans, padded 32)
#define TAB_BYTES ((CP_ENTRIES + CT_ENTRIES) * 16)   // 147456 B

__device__ __forceinline__ float knotv(int i) {
    int t = i - 3;
    t = t < 0 ? 0 : (t > 29 ? 29 : t);
    return (float)t * (1.0f / 29.0f);
}

// Reference Cox-de Boor values only (fill phase, runs 4x29 times per block).
__device__ void basisVal3(float u, int span, float* __restrict__ Nb) {
    float left[4], right[4];
    float ndu[4][4];
    ndu[0][0] = 1.0f;
#pragma unroll
    for (int j = 1; j <= 3; ++j) {
        left[j]  = u - knotv(span + 1 - j);
        right[j] = knotv(span + j) - u;
        float saved = 0.0f;
#pragma unroll
        for (int r = 0; r < j; ++r) {
            float den = right[r + 1] + left[j - r];
            float tmp = ndu[r][j - 1] / den;
            ndu[r][j] = saved + right[r + 1] * tmp;
            saved = left[j - r] * tmp;
        }
        ndu[j][j] = saved;
    }
    Nb[0] = ndu[0][3]; Nb[1] = ndu[1][3]; Nb[2] = ndu[2][3]; Nb[3] = ndu[3][3];
}

extern "C" __global__ void __launch_bounds__(NTHREADS, 1)
nurbs_surface_kernel(const float2* __restrict__ ep,
                     const float*  __restrict__ cp,
                     float4* __restrict__ out,
                     int n)
{
    extern __shared__ float4 smem_tab[];
    float4* __restrict__ tab  = smem_tab;                 // control points
    float4* __restrict__ ctab = smem_tab + CP_ENTRIES;    // basis poly coeffs

    const int tid   = threadIdx.x;
    const int lane8 = tid & 7;

    // ---- fill control-point table (8x replicated, bank-column striped) ----
#pragma unroll
    for (int i = 0; i < 8; ++i) {
        int e = i * NTHREADS + tid;
        int cell = e >> 3;
        tab[e] = make_float4(cp[3 * cell + 0], cp[3 * cell + 1], cp[3 * cell + 2], 1.0f);
    }

    // ---- fill basis coefficient table: fit cubic through 4 samples ----
    // span se, local t = u*29 - se; sample t = k/3, k=0..3 (polynomial piece
    // of the basis on this span -> fit is exact up to roundoff).
    if (tid < 29) {
        int se = tid;
        float y[4][4];
#pragma unroll
        for (int k = 0; k < 4; ++k) {
            float uk = ((float)se + (float)k * (1.0f / 3.0f)) * (1.0f / 29.0f);
            basisVal3(uk, se + 3, y[k]);
        }
#pragma unroll
        for (int r = 0; r < 4; ++r) {
            float y0 = y[0][r], y1 = y[1][r], y2 = y[2][r], y3 = y[3][r];
            // inverse Vandermonde, nodes t = {0, 1/3, 2/3, 1}
            float a0 = y0;
            float a1 = 0.5f * (-11.0f * y0 + 18.0f * y1 - 9.0f * y2 + 2.0f * y3);
            float a2 = 4.5f * (2.0f * y0 - 5.0f * y1 + 4.0f * y2 - y3);
            float a3 = 4.5f * (-y0 + 3.0f * y1 - 3.0f * y2 + y3);
            float4 c = make_float4(a0, a1, a2, a3);
            int base = (se * 4 + r) * 8;
#pragma unroll
            for (int col = 0; col < 8; ++col) ctab[base + col] = c;
        }
    }
    __syncthreads();

    float4* __restrict__ outn = out + n;

    for (int idx = blockIdx.x * NTHREADS + tid; idx < n; idx += NBLOCKS * NTHREADS) {
        float2 uv = ep[idx];

        float ue = uv.x * 29.0f;
        float vn = uv.y * 29.0f;
        int se = (int)floorf(ue);
        se = se < 0 ? 0 : (se > 28 ? 28 : se);
        int sn = (int)floorf(vn);
        sn = sn < 0 ? 0 : (sn > 28 ? 28 : sn);
        float tu = ue - (float)se;
        float tv = vn - (float)sn;

        // ---- basis via Horner on table coefficients (conflict-free LDS) ----
        float Nu[4], Du[4], Nv[4], Dv[4];
        {
            const float4* __restrict__ cu = ctab + (se * 4) * 8 + lane8;
            const float4* __restrict__ cv = ctab + (sn * 4) * 8 + lane8;
#pragma unroll
            for (int r = 0; r < 4; ++r) {
                float4 c = cu[r * 8];
                Nu[r] = fmaf(fmaf(fmaf(c.w, tu, c.z), tu, c.y), tu, c.x);
                Du[r] = fmaf(fmaf(3.0f * c.w, tu, c.z + c.z), tu, c.y);
            }
#pragma unroll
            for (int r = 0; r < 4; ++r) {
                float4 c = cv[r * 8];
                Nv[r] = fmaf(fmaf(fmaf(c.w, tv, c.z), tv, c.y), tv, c.x);
                Dv[r] = fmaf(fmaf(3.0f * c.w, tv, c.z + c.z), tv, c.y);
            }
        }
        // (Du,Dv are d/dt; true d/du = 29*d/dt and ref multiplies by p=3 —
        //  uniform positive scales on both partials cancel after normalization.)

        // ---- separable tensor contraction, conflict-free gather ----
        const float4* __restrict__ p = tab + ((se * NCP + sn) * 8 + lane8);

        float px=0.f,py=0.f,pz=0.f;   // surface point (homogeneous w == 1)
        float ex=0.f,ey=0.f,ez=0.f;   // ~ d/du
        float fx=0.f,fy=0.f,fz=0.f;   // ~ d/dv
#pragma unroll
        for (int r = 0; r < 4; ++r) {
            float ax=0.f, ay=0.f, az=0.f;
            float bx=0.f, by=0.f, bz=0.f;
#pragma unroll
            for (int s = 0; s < 4; ++s) {
                float4 g = p[(r * NCP + s) * 8];
                float nv = Nv[s], dv = Dv[s];
                ax = fmaf(nv, g.x, ax); ay = fmaf(nv, g.y, ay); az = fmaf(nv, g.z, az);
                bx = fmaf(dv, g.x, bx); by = fmaf(dv, g.y, by); bz = fmaf(dv, g.z, bz);
            }
            float nu = Nu[r], du = Du[r];
            px = fmaf(nu, ax, px); py = fmaf(nu, ay, py); pz = fmaf(nu, az, pz);
            ex = fmaf(du, ax, ex); ey = fmaf(du, ay, ey); ez = fmaf(du, az, ez);
            fx = fmaf(nu, bx, fx); fy = fmaf(nu, by, fy); fz = fmaf(nu, bz, fz);
        }

        // normal = normalize(cross(d_e, d_n))
        float cx = ey * fz - ez * fy;
        float cy = ez * fx - ex * fz;
        float cz = ex * fy - ey * fx;
        float il = rsqrtf(cx * cx + cy * cy + cz * cz);

        out[idx]  = make_float4(px, py, pz, 1.0f);
        outn[idx] = make_float4(cx * il, cy * il, cz * il, 0.0f);
    }
}

extern "C" void kernel_launch(void* const* d_in, const int* in_sizes, int n_in,
                              void* d_out, int out_size)
{
    const float2* ep = (const float2*)d_in[0];   // evaluation_points (N,2)
    const float*  cp = (const float*)d_in[1];    // control_points (32,32,3)
    int n = in_sizes[0] / 2;
    float4* out = (float4*)d_out;

    cudaFuncSetAttribute(nurbs_surface_kernel,
                         cudaFuncAttributeMaxDynamicSharedMemorySize, TAB_BYTES);

    nurbs_surface_kernel<<<NBLOCKS, NTHREADS, TAB_BYTES>>>(ep, cp, out, n);
}

// round 9
// speedup vs baseline: 1.0597x; 1.0597x over previous
#include <cuda_runtime.h>

// NURBS surface eval: DEG=3, N_CP=32x32, N_EVAL=2,000,000.
// Clamped-uniform knots: knot(i) = clamp(i-3,0,29)/29, span = floor(u*29)+3.
// Output: d_out[0..4N) = points (x,y,z,1); d_out[4N..8N) = normals (nx,ny,nz,0).
//
// R8 = R5 structure (8x bank-column-replicated smem table, zero LDS conflicts,
// persistent 148x1024) with the basis ALU chains surgically removed:
//  * rcp.approx.f32 on float denominators (idle MUFU) replaces all the
//    integer-knot-diff ISETP/SEL reciprocal chains.
//  * j=3 Cox-de Boor quotients reused directly as derivative t_r (no recompute).
//  * Only 4 knot clamps per direction (k0,k1 are range-safe), single FMNMX each.
// Partition of unity => homogeneous w == 1 (no divide).

#define NCP 32
#define NTHREADS 1024
#define NBLOCKS 148
#define TAB_BYTES (NCP * NCP * 8 * 16)   // 128 KB

__device__ __forceinline__ float rcpa(float x) {
    float r; asm("rcp.approx.f32 %0, %1;" : "=f"(r) : "f"(x)); return r;
}

// Cox-de Boor p=3: values N[0..3], derivatives D[0..3] (already *p).
// sef = (float)se, se in [0,28]. No integer knot work, no selects.
__device__ __forceinline__ void basis3(float u, float sef,
                                       float* __restrict__ Nb, float* __restrict__ Db) {
    const float C = 1.0f / 29.0f;
    // local knots: knot(span+q) = clamp(se+q,0,29)*C for q=-2..3
    float km2 = fmaxf((sef - 2.0f) * C, 0.0f);
    float km1 = fmaxf((sef - 1.0f) * C, 0.0f);
    float k0  = sef * C;                        // se in [0,28]: no clamp needed
    float k1  = (sef + 1.0f) * C;               // <= 1 always: no clamp needed
    float k2  = fminf((sef + 2.0f) * C, 1.0f);
    float k3  = fminf((sef + 3.0f) * C, 1.0f);

    float left[4], right[4];
    left[1]  = u - k0;  left[2]  = u - km1; left[3]  = u - km2;
    right[1] = k1 - u;  right[2] = k2 - u;  right[3] = k3 - u;

    float ndu[4][4];
    ndu[0][0] = 1.0f;
    float t3[3];
#pragma unroll
    for (int j = 1; j <= 3; ++j) {
        float saved = 0.0f;
#pragma unroll
        for (int r = 0; r < j; ++r) {
            float den = right[r + 1] + left[j - r];
            float tmp = ndu[r][j - 1] * rcpa(den);
            if (j == 3) t3[r] = tmp;            // == ndu[r][2]/ndu[3][r]
            ndu[r][j] = fmaf(right[r + 1], tmp, saved);
            saved = left[j - r] * tmp;
        }
        ndu[j][j] = saved;
    }
    Nb[0] = ndu[0][3]; Nb[1] = ndu[1][3]; Nb[2] = ndu[2][3]; Nb[3] = ndu[3][3];
    Db[0] = -3.0f * t3[0];
    Db[1] = 3.0f * (t3[0] - t3[1]);
    Db[2] = 3.0f * (t3[1] - t3[2]);
    Db[3] = 3.0f * t3[2];
}

extern "C" __global__ void __launch_bounds__(NTHREADS, 1)
nurbs_surface_kernel(const float2* __restrict__ ep,
                     const float*  __restrict__ cp,
                     float4* __restrict__ out,
                     int n)
{
    extern __shared__ float4 tab[];   // [1024 cells][8 bank-columns]
    const int tid   = threadIdx.x;
    const int lane8 = tid & 7;

#pragma unroll
    for (int i = 0; i < 8; ++i) {
        int e = i * NTHREADS + tid;
        int cell = e >> 3;
        tab[e] = make_float4(cp[3 * cell + 0], cp[3 * cell + 1], cp[3 * cell + 2], 1.0f);
    }
    __syncthreads();

    float4* __restrict__ outn = out + n;

    for (int idx = blockIdx.x * NTHREADS + tid; idx < n; idx += NBLOCKS * NTHREADS) {
        float2 uv = ep[idx];

        int se = (int)floorf(uv.x * 29.0f);
        se = se < 0 ? 0 : (se > 28 ? 28 : se);
        int sn = (int)floorf(uv.y * 29.0f);
        sn = sn < 0 ? 0 : (sn > 28 ? 28 : sn);

        float Nu[4], Du[4], Nv[4], Dv[4];
        basis3(uv.x, (float)se, Nu, Du);
        basis3(uv.y, (float)sn, Nv, Dv);

        // Conflict-free gather base: this lane's private bank column.
        const float4* __restrict__ p = tab + ((se * NCP + sn) * 8 + lane8);

        float px=0.f,py=0.f,pz=0.f;   // surface point (homogeneous w == 1)
        float ex=0.f,ey=0.f,ez=0.f;   // d/du
        float fx=0.f,fy=0.f,fz=0.f;   // d/dv
#pragma unroll
        for (int r = 0; r < 4; ++r) {
            float ax=0.f, ay=0.f, az=0.f;
            float bx=0.f, by=0.f, bz=0.f;
#pragma unroll
            for (int s = 0; s < 4; ++s) {
                float4 g = p[(r * NCP + s) * 8];
                float nv = Nv[s], dv = Dv[s];
                ax = fmaf(nv, g.x, ax); ay = fmaf(nv, g.y, ay); az = fmaf(nv, g.z, az);
                bx = fmaf(dv, g.x, bx); by = fmaf(dv, g.y, by); bz = fmaf(dv, g.z, bz);
            }
            float nu = Nu[r], du = Du[r];
            px = fmaf(nu, ax, px); py = fmaf(nu, ay, py); pz = fmaf(nu, az, pz);
            ex = fmaf(du, ax, ex); ey = fmaf(du, ay, ey); ez = fmaf(du, az, ez);
            fx = fmaf(nu, bx, fx); fy = fmaf(nu, by, fy); fz = fmaf(nu, bz, fz);
        }

        // normal = normalize(cross(d_e, d_n))
        float cx = ey * fz - ez * fy;
        float cy = ez * fx - ex * fz;
        float cz = ex * fy - ey * fx;
        float il = rsqrtf(cx * cx + cy * cy + cz * cz);

        out[idx]  = make_float4(px, py, pz, 1.0f);
        outn[idx] = make_float4(cx * il, cy * il, cz * il, 0.0f);
    }
}

extern "C" void kernel_launch(void* const* d_in, const int* in_sizes, int n_in,
                              void* d_out, int out_size)
{
    const float2* ep = (const float2*)d_in[0];   // evaluation_points (N,2)
    const float*  cp = (const float*)d_in[1];    // control_points (32,32,3)
    int n = in_sizes[0] / 2;
    float4* out = (float4*)d_out;

    cudaFuncSetAttribute(nurbs_surface_kernel,
                         cudaFuncAttributeMaxDynamicSharedMemorySize, TAB_BYTES);

    nurbs_surface_kernel<<<NBLOCKS, NTHREADS, TAB_BYTES>>>(ep, cp, out, n);
}

// round 10
// speedup vs baseline: 1.0877x; 1.0264x over previous
#include <cuda_runtime.h>

// NURBS surface eval: DEG=3, N_CP=32x32, N_EVAL=2,000,000.
// Clamped-uniform knots: knot(i) = clamp(i-3,0,29)/29, span = floor(u*29)+3.
// Output: d_out[0..4N) = points (x,y,z,1); d_out[4N..8N) = normals (nx,ny,nz,0).
//
// R10 = coefficient-table basis (20% fewer instructions than Cox-de Boor, per
// R7 measurement) + stall fixes that R7 lacked:
//  * uv prefetched one grid-stride iteration ahead (streaming LDG off the
//    critical path).
//  * 6 coeff LDS instead of 8: N3/D3 from partition of unity (sum N = 1,
//    sum D = 0 — exact identities of the basis).
//  * u/v Horner chains independent + cell base computed early so the 16
//    conflict-free cell LDS can hoist above the Horners.
// Basis N_r on span se is a fixed cubic in t = u*29 - se; 29x3 float4 coeff
// table (N3 derived), 8x bank-column-replicated like the control-point table
// -> ALL smem gathers provably conflict-free for random spans.
// Derivative scales (29 per direction, p=3) are uniform positive on both
// partials -> cancel in the normalized cross product. Partition of unity
// -> homogeneous w == 1 (no divide).

#define NCP 32
#define NTHREADS 1024
#define NBLOCKS 148
#define CP_ENTRIES (NCP * NCP * 8)           // 8192 float4 = 128 KB
#define CT_STRIDE  (3 * 8)                   // 3 float4 x 8 bank-columns per span
#define CT_ENTRIES (32 * CT_STRIDE)          // padded to 32 spans = 12 KB
#define TAB_BYTES ((CP_ENTRIES + CT_ENTRIES) * 16)

__device__ __forceinline__ float knotv(int i) {
    int t = i - 3;
    t = t < 0 ? 0 : (t > 29 ? 29 : t);
    return (float)t * (1.0f / 29.0f);
}

// Reference Cox-de Boor values (fill phase only; 4x29 evals per block).
__device__ void basisVal3(float u, int span, float* __restrict__ Nb) {
    float left[4], right[4];
    float ndu[4][4];
    ndu[0][0] = 1.0f;
#pragma unroll
    for (int j = 1; j <= 3; ++j) {
        left[j]  = u - knotv(span + 1 - j);
        right[j] = knotv(span + j) - u;
        float saved = 0.0f;
#pragma unroll
        for (int r = 0; r < j; ++r) {
            float den = right[r + 1] + left[j - r];
            float tmp = ndu[r][j - 1] / den;
            ndu[r][j] = saved + right[r + 1] * tmp;
            saved = left[j - r] * tmp;
        }
        ndu[j][j] = saved;
    }
    Nb[0] = ndu[0][3]; Nb[1] = ndu[1][3]; Nb[2] = ndu[2][3]; Nb[3] = ndu[3][3];
}

extern "C" __global__ void __launch_bounds__(NTHREADS, 1)
nurbs_surface_kernel(const float2* __restrict__ ep,
                     const float*  __restrict__ cp,
                     float4* __restrict__ out,
                     int n)
{
    extern __shared__ float4 smem_tab[];
    float4* __restrict__ tab  = smem_tab;                 // control points
    float4* __restrict__ ctab = smem_tab + CP_ENTRIES;    // basis cubic coeffs

    const int tid   = threadIdx.x;
    const int lane8 = tid & 7;

    // ---- control-point table (8x replicated, bank-column striped) ----
#pragma unroll
    for (int i = 0; i < 8; ++i) {
        int e = i * NTHREADS + tid;
        int cell = e >> 3;
        tab[e] = make_float4(cp[3 * cell + 0], cp[3 * cell + 1], cp[3 * cell + 2], 1.0f);
    }

    // ---- coeff table: exact cubic fit per span (only N0..N2 stored) ----
    if (tid < 29) {
        int se = tid;
        float y[4][4];
#pragma unroll
        for (int k = 0; k < 4; ++k) {
            float uk = ((float)se + (float)k * (1.0f / 3.0f)) * (1.0f / 29.0f);
            basisVal3(uk, se + 3, y[k]);
        }
#pragma unroll
        for (int r = 0; r < 3; ++r) {
            float y0 = y[0][r], y1 = y[1][r], y2 = y[2][r], y3 = y[3][r];
            // inverse Vandermonde, nodes t = {0, 1/3, 2/3, 1}
            float a0 = y0;
            float a1 = 0.5f * (-11.0f * y0 + 18.0f * y1 - 9.0f * y2 + 2.0f * y3);
            float a2 = 4.5f * (2.0f * y0 - 5.0f * y1 + 4.0f * y2 - y3);
            float a3 = 4.5f * (-y0 + 3.0f * y1 - 3.0f * y2 + y3);
            float4 c = make_float4(a0, a1, a2, a3);
            int base = se * CT_STRIDE + r * 8;
#pragma unroll
            for (int col = 0; col < 8; ++col) ctab[base + col] = c;
        }
    }
    __syncthreads();

    float4* __restrict__ outn = out + n;
    const int stride = NBLOCKS * NTHREADS;
    int idx = blockIdx.x * NTHREADS + tid;
    if (idx >= n) return;

    float2 uv = ep[idx];                      // prologue load

    for (; idx < n; idx += stride) {
        float ue = uv.x * 29.0f;
        float vn = uv.y * 29.0f;
        int se = (int)floorf(ue);
        se = se < 0 ? 0 : (se > 28 ? 28 : se);
        int sn = (int)floorf(vn);
        sn = sn < 0 ? 0 : (sn > 28 ? 28 : sn);
        float tu = ue - (float)se;
        float tv = vn - (float)sn;

        // prefetch next iteration's uv (off the critical path)
        int nidx = idx + stride;
        if (nidx < n) uv = ep[nidx];

        // cell-gather base early so cell LDS can hoist above the Horners
        const float4* __restrict__ p = tab + ((se * NCP + sn) * 8 + lane8);
        const float4* __restrict__ cu = ctab + se * CT_STRIDE + lane8;
        const float4* __restrict__ cv = ctab + sn * CT_STRIDE + lane8;

        // ---- basis via Horner; N3/D3 from partition of unity ----
        float Nu[4], Du[4], Nv[4], Dv[4];
        {
            float snu = 0.f, sdu = 0.f, snv = 0.f, sdv = 0.f;
#pragma unroll
            for (int r = 0; r < 3; ++r) {
                float4 c = cu[r * 8];
                float Nr = fmaf(fmaf(fmaf(c.w, tu, c.z), tu, c.y), tu, c.x);
                float Dr = fmaf(fmaf(3.0f * c.w, tu, c.z + c.z), tu, c.y);
                Nu[r] = Nr; Du[r] = Dr; snu += Nr; sdu += Dr;
            }
#pragma unroll
            for (int r = 0; r < 3; ++r) {
                float4 c = cv[r * 8];
                float Nr = fmaf(fmaf(fmaf(c.w, tv, c.z), tv, c.y), tv, c.x);
                float Dr = fmaf(fmaf(3.0f * c.w, tv, c.z + c.z), tv, c.y);
                Nv[r] = Nr; Dv[r] = Dr; snv += Nr; sdv += Dr;
            }
            Nu[3] = 1.0f - snu; Du[3] = -sdu;
            Nv[3] = 1.0f - snv; Dv[3] = -sdv;
        }

        // ---- separable tensor contraction, conflict-free gather ----
        float px=0.f,py=0.f,pz=0.f;   // surface point (homogeneous w == 1)
        float ex=0.f,ey=0.f,ez=0.f;   // ~ d/du
        float fx=0.f,fy=0.f,fz=0.f;   // ~ d/dv
#pragma unroll
        for (int r = 0; r < 4; ++r) {
            float ax=0.f, ay=0.f, az=0.f;
            float bx=0.f, by=0.f, bz=0.f;
#pragma unroll
            for (int s = 0; s < 4; ++s) {
                float4 g = p[(r * NCP + s) * 8];
                float nv = Nv[s], dv = Dv[s];
                ax = fmaf(nv, g.x, ax); ay = fmaf(nv, g.y, ay); az = fmaf(nv, g.z, az);
                bx = fmaf(dv, g.x, bx); by = fmaf(dv, g.y, by); bz = fmaf(dv, g.z, bz);
            }
            float nu = Nu[r], du = Du[r];
            px = fmaf(nu, ax, px); py = fmaf(nu, ay, py); pz = fmaf(nu, az, pz);
            ex = fmaf(du, ax, ex); ey = fmaf(du, ay, ey); ez = fmaf(du, az, ez);
            fx = fmaf(nu, bx, fx); fy = fmaf(nu, by, fy); fz = fmaf(nu, bz, fz);
        }

        // normal = normalize(cross(d_e, d_n)); uniform scales cancel here
        float cx = ey * fz - ez * fy;
        float cy = ez * fx - ex * fz;
        float cz = ex * fy - ey * fx;
        float il = rsqrtf(cx * cx + cy * cy + cz * cz);

        out[idx]  = make_float4(px, py, pz, 1.0f);
        outn[idx] = make_float4(cx * il, cy * il, cz * il, 0.0f);
    }
}

extern "C" void kernel_launch(void* const* d_in, const int* in_sizes, int n_in,
                              void* d_out, int out_size)
{
    const float2* ep = (const float2*)d_in[0];   // evaluation_points (N,2)
    const float*  cp = (const float*)d_in[1];    // control_points (32,32,3)
    int n = in_sizes[0] / 2;
    float4* out = (float4*)d_out;

    cudaFuncSetAttribute(nurbs_surface_kernel,
                         cudaFuncAttributeMaxDynamicSharedMemorySize, TAB_BYTES);

    nurbs_surface_kernel<<<NBLOCKS, NTHREADS, TAB_BYTES>>>(ep, cp, out, n);
}